// round 3
// baseline (speedup 1.0000x reference)
#include <cuda_runtime.h>
#include <math.h>

// Problem constants (fixed by the reference)
#define NVAR 4000000
#define KFAC 2000000
#define DV 3
#define DC 6
#define EDGES (NVAR * DV)   // 12,000,000

// Single edge-message scratch buffer, variable-side edge order. 48MB.
// K1 writes Hsx into it; K2 updates it IN PLACE (each slot is gathered by
// exactly one factor thread, which reads before it writes -> race-free,
// deterministic); K3 reads it contiguously.
__device__ float g_msg[EDGES];

// ---------------------------------------------------------------------------
// Kernel 1: variable -> factor update. One thread per variable.
// ---------------------------------------------------------------------------
__global__ void __launch_bounds__(256)
var_update_kernel(const float2* __restrict__ ps,
                  const float2* __restrict__ Min,
                  const float*  __restrict__ Hxs_prev,
                  int n_vars)
{
    int n = blockIdx.x * blockDim.x + threadIdx.x;
    if (n >= n_vars) return;

    float2 m = Min[n];
    float2 p = ps[n];
    float prior = 0.5f * (__logf(m.x) - __logf(m.y))
                + 0.5f * (__logf(p.x) - __logf(p.y));

    float h0 = Hxs_prev[3 * n + 0];
    float h1 = Hxs_prev[3 * n + 1];
    float h2 = Hxs_prev[3 * n + 2];

    bool i0 = isinf(h0), i1 = isinf(h1), i2 = isinf(h2);
    int sure = (int)i0 + (int)i1 + (int)i2;

    float o0, o1, o2;
    if (sure == 0) {
        // hot path: extrinsic sums (inputs are finite random normals)
        float ll = (h0 + h1) + h2;
        o0 = prior + ll - h0;
        o1 = prior + ll - h1;
        o2 = prior + ll - h2;
    } else {
        float ll = (i0 ? 0.0f : h0) + (i1 ? 0.0f : h1) + (i2 ? 0.0f : h2);
        float ss = (i0 ? h0 : 0.0f) + (i1 ? h1 : 0.0f) + (i2 ? h2 : 0.0f);
        if (sure == 1) {
            float pl = prior + ll;
            o0 = i0 ? pl : ss;
            o1 = i1 ? pl : ss;
            o2 = i2 ? pl : ss;
        } else {
            float v = isnan(ss) ? 0.0f : (prior + ss);
            o0 = v; o1 = v; o2 = v;
        }
    }
    g_msg[3 * n + 0] = o0;
    g_msg[3 * n + 1] = o1;
    g_msg[3 * n + 2] = o2;
}

// ---------------------------------------------------------------------------
// Kernel 2: factor -> variable update, IN PLACE on g_msg. One thread per check.
// inv_perm is a permutation: each edge slot is owned by exactly one factor
// thread, which gathers it, computes, and scatters back to the same address.
// perm is never needed (perm[inv_perm[e]] == e), so K3 reads contiguously.
// ---------------------------------------------------------------------------
__global__ void __launch_bounds__(256)
fac_update_kernel(const int* __restrict__ inv_perm,
                  const int* __restrict__ x,
                  int n_fac)
{
    int a = blockIdx.x * blockDim.x + threadIdx.x;
    if (a >= n_fac) return;

    const int base = DC * a;
    int   idx[DC];
    float t[DC];
    bool  z[DC];

    // coalesced index load, then all gathers issued back-to-back for MLP
    #pragma unroll
    for (int k = 0; k < DC; k++) idx[k] = inv_perm[base + k];

    float v[DC];
    #pragma unroll
    for (int k = 0; k < DC; k++) v[k] = g_msg[idx[k]];

    int   nz = 0;
    float prod = 1.0f;
    #pragma unroll
    for (int k = 0; k < DC; k++) {
        t[k] = tanhf(v[k]);
        z[k] = (t[k] == 0.0f);
        nz += (int)z[k];
        prod *= z[k] ? 1.0f : t[k];
    }

    float sgn = 1.0f - 2.0f * (float)x[a];
    float pn  = sgn * prod;

    if (nz == 0) {
        #pragma unroll
        for (int k = 0; k < DC; k++)
            g_msg[idx[k]] = atanhf(pn / t[k]);
    } else if (nz == 1) {
        float ath = atanhf(pn);
        #pragma unroll
        for (int k = 0; k < DC; k++)
            g_msg[idx[k]] = z[k] ? ath : 0.0f;
    } else {
        #pragma unroll
        for (int k = 0; k < DC; k++)
            g_msg[idx[k]] = 0.0f;
    }
}

// ---------------------------------------------------------------------------
// Kernel 3: output beliefs. One thread per variable; contiguous reads.
// ---------------------------------------------------------------------------
__global__ void __launch_bounds__(256)
output_kernel(float2* __restrict__ Mout, int n_vars)
{
    int n = blockIdx.x * blockDim.x + threadIdx.x;
    if (n >= n_vars) return;

    float h0 = g_msg[3 * n + 0];
    float h1 = g_msg[3 * n + 1];
    float h2 = g_msg[3 * n + 2];

    float s = (h0 + h1) + h2;
    float d = tanhf(s);

    if (isnan(d)) {
        bool c0 = isinf(h0), c1 = isinf(h1), c2 = isinf(h2);
        if (c0 | c1 | c2) {
            float s2 = (c0 ? 0.0f : h0) + (c1 ? 0.0f : h1) + (c2 ? 0.0f : h2);
            d = tanhf(s2);
        }
    }

    float2 out;
    out.x = 0.5f + 0.5f * d;
    out.y = 0.5f - 0.5f * d;
    Mout[n] = out;
}

// ---------------------------------------------------------------------------
// Launch. Inputs (metadata order): ps[N,2] f32, Min[N,2] f32, Hxs_prev[N,3] f32,
// x[K,1] i32, perm[E] i32 (unused), inv_perm[E] i32. Output: M_out[N,2] f32.
// ---------------------------------------------------------------------------
extern "C" void kernel_launch(void* const* d_in, const int* in_sizes, int n_in,
                              void* d_out, int out_size)
{
    const float2* ps       = (const float2*)d_in[0];
    const float2* Min      = (const float2*)d_in[1];
    const float*  Hxs_prev = (const float*)d_in[2];
    const int*    x        = (const int*)d_in[3];
    const int*    inv_perm = (const int*)d_in[5];

    int n_vars = in_sizes[0] / 2;   // 4,000,000
    int n_fac  = in_sizes[3];       // 2,000,000

    const int T = 256;
    var_update_kernel<<<(n_vars + T - 1) / T, T>>>(ps, Min, Hxs_prev, n_vars);
    fac_update_kernel<<<(n_fac + T - 1) / T, T>>>(inv_perm, x, n_fac);
    output_kernel<<<(n_vars + T - 1) / T, T>>>((float2*)d_out, n_vars);
}